// round 7
// baseline (speedup 1.0000x reference)
#include <cuda_runtime.h>
#include <cuda_bf16.h>
#include <math.h>

// ---------------- problem constants ----------------
#define Bc   4
#define Sc   256
#define SKc  512
#define Dc   1024
#define NHc  16
#define NKVc 4
#define HDc  64
#define KVDc (NKVc*HDc)   // 256
#define DEc  4096
#define NEc  8
#define LN_EPS 1e-5f
#define QSCALE 0.125f     // HD^-0.5

// ---------------- scratch (device globals; no allocs allowed) ----------------
__device__ float g_ln  [Bc*Sc*Dc];                       // 4 MB  (reused for ln1/ln2/ln3)
__device__ float g_q   [Bc*Sc*Dc];                       // 4 MB
__device__ float g_k   [Bc*SKc*KVDc];                    // 2 MB  (self uses first B*S rows)
__device__ float g_v   [Bc*SKc*KVDc];                    // 2 MB
__device__ float g_sc  [(size_t)Bc*NHc*Sc*SKc];          // 32 MB (scores, max Skv=512)
__device__ float g_ctx [Bc*Sc*Dc];                       // 4 MB
__device__ float g_res [Bc*Sc*Dc];                       // 4 MB  (running hidden)
__device__ float g_t1  [(size_t)NEc*Bc*Sc*DEc];          // 128 MB (x@w1, then h)
__device__ float g_t3  [(size_t)NEc*Bc*Sc*DEc];          // 128 MB (x@w3)
__device__ float g_pout[(size_t)NEc*Bc*Sc*Dc];           // 32 MB (per-pair expert out)
__device__ float g_coef[NEc*Bc];

// ---------------- routing ----------------
__global__ void k_route(const int* __restrict__ langs) {
    if (threadIdx.x == 0 && blockIdx.x == 0) {
        for (int b = 0; b < Bc; b++) {
            int l0 = langs[2*b], l1 = langs[2*b+1];
            int cnt = (l0 > 3) + (l1 > 3);
            float rw = (cnt == 0) ? 1.f : 1.f / (float)cnt;
            for (int e = 0; e < NEc; e++) {
                int code = 4 + e;
                g_coef[e*Bc + b] = ((l0 == code) || (l1 == code)) ? rw : 0.f;
            }
        }
    }
}

// ---------------- layernorm (block per row) ----------------
__global__ void k_ln(const float* __restrict__ x, const float* __restrict__ g,
                     const float* __restrict__ bta, float* __restrict__ y) {
    int row = blockIdx.x;
    int tid = threadIdx.x;
    const float* xr = x + (size_t)row * Dc;
    float s = 0.f, s2 = 0.f;
    for (int i = tid; i < Dc; i += 256) { float v = xr[i]; s += v; s2 += v*v; }
    __shared__ float r1[256], r2[256];
    r1[tid] = s; r2[tid] = s2; __syncthreads();
    for (int off = 128; off > 0; off >>= 1) {
        if (tid < off) { r1[tid] += r1[tid+off]; r2[tid] += r2[tid+off]; }
        __syncthreads();
    }
    float mean = r1[0] * (1.f/Dc);
    float var  = r2[0] * (1.f/Dc) - mean*mean;
    float inv  = rsqrtf(var + LN_EPS);
    for (int i = tid; i < Dc; i += 256)
        y[(size_t)row*Dc + i] = (xr[i] - mean) * inv * g[i] + bta[i];
}

// ---------------- generic 128x128x8 SGEMM body ----------------
// mode: 0 = plain, 1 = +bias, 2 = (+bias)*scale, 3 = +bias+res
__device__ __forceinline__ void sgemm_tile(
    const float* __restrict__ A, const float* __restrict__ Bm, float* __restrict__ C,
    int M, int N, int K,
    const float* __restrict__ bias, const float* __restrict__ res,
    float scale, int mode)
{
    __shared__ float As[8][128];
    __shared__ float Bs[8][128];
    int tid = threadIdx.x;
    int bm = blockIdx.y * 128;
    int bn = blockIdx.x * 128;
    int tx = tid & 15, ty = tid >> 4;

    float acc[8][8];
    #pragma unroll
    for (int i = 0; i < 8; i++)
        #pragma unroll
        for (int j = 0; j < 8; j++) acc[i][j] = 0.f;

    int aRow = tid >> 1;             // 0..127
    int aCol = (tid & 1) * 4;        // 0 or 4
    int bRow = tid >> 5;             // 0..7
    int bCol = (tid & 31) * 4;       // 0..124

    const float* Ag = A  + (size_t)(bm + aRow) * K + aCol;
    const float* Bg = Bm + (size_t)bRow * N + bn + bCol;

    for (int k0 = 0; k0 < K; k0 += 8) {
        float4 a4 = *reinterpret_cast<const float4*>(Ag + k0);
        As[aCol+0][aRow] = a4.x;
        As[aCol+1][aRow] = a4.y;
        As[aCol+2][aRow] = a4.z;
        As[aCol+3][aRow] = a4.w;
        float4 b4 = *reinterpret_cast<const float4*>(Bg + (size_t)k0 * N);
        *reinterpret_cast<float4*>(&Bs[bRow][bCol]) = b4;
        __syncthreads();
        #pragma unroll
        for (int kk = 0; kk < 8; kk++) {
            float ra[8], rb[8];
            #pragma unroll
            for (int i = 0; i < 8; i++) ra[i] = As[kk][ty*8 + i];
            #pragma unroll
            for (int j = 0; j < 8; j++) rb[j] = Bs[kk][tx*8 + j];
            #pragma unroll
            for (int i = 0; i < 8; i++)
                #pragma unroll
                for (int j = 0; j < 8; j++)
                    acc[i][j] += ra[i] * rb[j];
        }
        __syncthreads();
    }
    #pragma unroll
    for (int i = 0; i < 8; i++) {
        int r = bm + ty*8 + i;
        #pragma unroll
        for (int j = 0; j < 8; j++) {
            int c = bn + tx*8 + j;
            float v = acc[i][j];
            if (mode == 1)      v = v + bias[c];
            else if (mode == 2) v = (v + bias[c]) * scale;
            else if (mode == 3) v = v + bias[c] + res[(size_t)r*N + c];
            C[(size_t)r*N + c] = v;
        }
    }
}

__global__ void k_gemm(const float* __restrict__ A, const float* __restrict__ B,
                       float* __restrict__ C, int M, int N, int K,
                       const float* __restrict__ bias, const float* __restrict__ res,
                       float scale, int mode)
{
    sgemm_tile(A, B, C, M, N, K, bias, res, scale, mode);
}

// ---------------- attention: scores = Q K^T + mask ----------------
// grid: (Sq/64, Skv/64, B*NH); q layout [b,s,h*64+d] (pre-scaled), k layout [b,s,kvh*64+d]
__global__ void k_scores(const float* __restrict__ q, const float* __restrict__ kmat,
                         const float* __restrict__ mask, float* __restrict__ out, int Skv)
{
    int z = blockIdx.z;
    int b = z / NHc, h = z % NHc, kvh = h >> 2;
    int q0 = blockIdx.x * 64, k0 = blockIdx.y * 64;
    __shared__ float Qs[64][65];
    __shared__ float Ks[64][65];
    int tid = threadIdx.x;

    for (int t = tid; t < 1024; t += 256) {      // 64 rows x 16 float4
        int r = t >> 4, c = (t & 15) << 2;
        float4 v = *reinterpret_cast<const float4*>(
            q + (size_t)(b*Sc + q0 + r)*Dc + h*HDc + c);
        Qs[r][c] = v.x; Qs[r][c+1] = v.y; Qs[r][c+2] = v.z; Qs[r][c+3] = v.w;
        float4 w = *reinterpret_cast<const float4*>(
            kmat + (size_t)(b*Skv + k0 + r)*KVDc + kvh*HDc + c);
        Ks[r][c] = w.x; Ks[r][c+1] = w.y; Ks[r][c+2] = w.z; Ks[r][c+3] = w.w;
    }
    __syncthreads();

    int tx = tid & 15, ty = tid >> 4;
    float acc[4][4];
    #pragma unroll
    for (int i = 0; i < 4; i++)
        #pragma unroll
        for (int j = 0; j < 4; j++) acc[i][j] = 0.f;

    #pragma unroll 8
    for (int kk = 0; kk < 64; kk++) {
        float a[4], bb[4];
        #pragma unroll
        for (int i = 0; i < 4; i++) a[i]  = Qs[ty*4 + i][kk];
        #pragma unroll
        for (int j = 0; j < 4; j++) bb[j] = Ks[tx*4 + j][kk];
        #pragma unroll
        for (int i = 0; i < 4; i++)
            #pragma unroll
            for (int j = 0; j < 4; j++) acc[i][j] += a[i] * bb[j];
    }
    #pragma unroll
    for (int i = 0; i < 4; i++) {
        int qr = q0 + ty*4 + i;
        #pragma unroll
        for (int j = 0; j < 4; j++) {
            int kc = k0 + tx*4 + j;
            out[((size_t)z*Sc + qr)*Skv + kc] =
                acc[i][j] + mask[((size_t)b*Sc + qr)*Skv + kc];
        }
    }
}

// ---------------- row softmax (warp per row) ----------------
__global__ void k_softmax(float* __restrict__ s, int L) {
    int row  = blockIdx.x * 8 + (threadIdx.x >> 5);
    int lane = threadIdx.x & 31;
    float* p = s + (size_t)row * L;
    float m = -3.4e38f;
    for (int i = lane; i < L; i += 32) m = fmaxf(m, p[i]);
    #pragma unroll
    for (int off = 16; off > 0; off >>= 1) m = fmaxf(m, __shfl_xor_sync(0xffffffffu, m, off));
    float sum = 0.f;
    for (int i = lane; i < L; i += 32) { float e = __expf(p[i] - m); p[i] = e; sum += e; }
    #pragma unroll
    for (int off = 16; off > 0; off >>= 1) sum += __shfl_xor_sync(0xffffffffu, sum, off);
    float inv = 1.f / sum;
    for (int i = lane; i < L; i += 32) p[i] *= inv;
}

// ---------------- attention: ctx = P V ----------------
// grid: (Sq/64, 1, B*NH); writes ctx[b,s,h*64+d]
__global__ void k_pv(const float* __restrict__ sm, const float* __restrict__ v,
                     float* __restrict__ ctx, int Skv)
{
    int z = blockIdx.z;
    int b = z / NHc, h = z % NHc, kvh = h >> 2;
    int q0 = blockIdx.x * 64;
    __shared__ float Ps[64][65];
    __shared__ float Vs[64][65];
    int tid = threadIdx.x;
    int tx = tid & 15, ty = tid >> 4;

    float acc[4][4];
    #pragma unroll
    for (int i = 0; i < 4; i++)
        #pragma unroll
        for (int j = 0; j < 4; j++) acc[i][j] = 0.f;

    for (int kc = 0; kc < Skv; kc += 64) {
        for (int t = tid; t < 1024; t += 256) {
            int r = t >> 4, c = (t & 15) << 2;
            float4 pv = *reinterpret_cast<const float4*>(
                sm + ((size_t)z*Sc + q0 + r)*Skv + kc + c);
            Ps[r][c] = pv.x; Ps[r][c+1] = pv.y; Ps[r][c+2] = pv.z; Ps[r][c+3] = pv.w;
            float4 vv = *reinterpret_cast<const float4*>(
                v + (size_t)(b*Skv + kc + r)*KVDc + kvh*HDc + c);
            Vs[r][c] = vv.x; Vs[r][c+1] = vv.y; Vs[r][c+2] = vv.z; Vs[r][c+3] = vv.w;
        }
        __syncthreads();
        #pragma unroll 8
        for (int kk = 0; kk < 64; kk++) {
            float a[4], bb[4];
            #pragma unroll
            for (int i = 0; i < 4; i++) a[i]  = Ps[ty*4 + i][kk];
            #pragma unroll
            for (int j = 0; j < 4; j++) bb[j] = Vs[kk][tx*4 + j];
            #pragma unroll
            for (int i = 0; i < 4; i++)
                #pragma unroll
                for (int j = 0; j < 4; j++) acc[i][j] += a[i] * bb[j];
        }
        __syncthreads();
    }
    #pragma unroll
    for (int i = 0; i < 4; i++) {
        int qr = q0 + ty*4 + i;
        #pragma unroll
        for (int j = 0; j < 4; j++)
            ctx[(size_t)(b*Sc + qr)*Dc + h*HDc + tx*4 + j] = acc[i][j];
    }
}

// ---------------- MoE GEMMs (early-exit on coef==0) ----------------
__global__ void k_moe_up(const float* __restrict__ x, const float* __restrict__ W,
                         float* __restrict__ out)
{
    int p = blockIdx.z;
    if (g_coef[p] == 0.f) return;
    int e = p / Bc, b = p % Bc;
    sgemm_tile(x + (size_t)b*Sc*Dc, W + (size_t)e*Dc*DEc, out + (size_t)p*Sc*DEc,
               Sc, DEc, Dc, nullptr, nullptr, 1.f, 0);
}

__global__ void k_moe_down(const float* __restrict__ h, const float* __restrict__ W,
                           float* __restrict__ out)
{
    int p = blockIdx.z;
    if (g_coef[p] == 0.f) return;
    int e = p / Bc;
    sgemm_tile(h + (size_t)p*Sc*DEc, W + (size_t)e*DEc*Dc, out + (size_t)p*Sc*Dc,
               Sc, Dc, DEc, nullptr, nullptr, 1.f, 0);
}

__device__ __forceinline__ float gelu_exact(float x) {
    return 0.5f * x * (1.f + erff(x * 0.70710678118654752f));
}

// h = gelu(t1) * t3, stored back into t1. grid: (S*DE/1024, E*B)
__global__ void k_moe_act(float* __restrict__ t1, const float* __restrict__ t3) {
    int p = blockIdx.y;
    if (g_coef[p] == 0.f) return;
    size_t base = (size_t)p*Sc*DEc + ((size_t)blockIdx.x*256 + threadIdx.x)*4;
    float4 a = *reinterpret_cast<float4*>(t1 + base);
    float4 c = *reinterpret_cast<const float4*>(t3 + base);
    a.x = gelu_exact(a.x) * c.x;
    a.y = gelu_exact(a.y) * c.y;
    a.z = gelu_exact(a.z) * c.z;
    a.w = gelu_exact(a.w) * c.w;
    *reinterpret_cast<float4*>(t1 + base) = a;
}

// out = res + sum_e coef[e,b] * pout[e,b]
__global__ void k_final(const float* __restrict__ res, const float* __restrict__ pout,
                        float* __restrict__ out)
{
    int idx = blockIdx.x * 256 + threadIdx.x;
    int b   = idx / (Sc*Dc);
    int off = idx - b*(Sc*Dc);
    float v = res[idx];
    #pragma unroll
    for (int e = 0; e < NEc; e++) {
        float cf = g_coef[e*Bc + b];
        if (cf != 0.f) v += cf * pout[(size_t)(e*Bc + b)*Sc*Dc + off];
    }
    out[idx] = v;
}

// ---------------- launch ----------------
extern "C" void kernel_launch(void* const* d_in, const int* in_sizes, int n_in,
                              void* d_out, int out_size)
{
    (void)in_sizes; (void)n_in; (void)out_size;
    const float* hid   = (const float*)d_in[0];
    const float* enc   = (const float*)d_in[1];
    const float* amask = (const float*)d_in[2];
    const float* emask = (const float*)d_in[3];
    const int*   langs = (const int*)  d_in[4];
    const float* ln1g  = (const float*)d_in[5];
    const float* ln1b  = (const float*)d_in[6];
    const float* saqw  = (const float*)d_in[7];
    const float* saqb  = (const float*)d_in[8];
    const float* sakw  = (const float*)d_in[9];
    const float* sakb  = (const float*)d_in[10];
    const float* savw  = (const float*)d_in[11];
    const float* savb  = (const float*)d_in[12];
    const float* saow  = (const float*)d_in[13];
    const float* saob  = (const float*)d_in[14];
    const float* ln2g  = (const float*)d_in[15];
    const float* ln2b  = (const float*)d_in[16];
    const float* caqw  = (const float*)d_in[17];
    const float* caqb  = (const float*)d_in[18];
    const float* cakw  = (const float*)d_in[19];
    const float* cakb  = (const float*)d_in[20];
    const float* cavw  = (const float*)d_in[21];
    const float* cavb  = (const float*)d_in[22];
    const float* caow  = (const float*)d_in[23];
    const float* caob  = (const float*)d_in[24];
    const float* ln3g  = (const float*)d_in[25];
    const float* ln3b  = (const float*)d_in[26];
    const float* w1    = (const float*)d_in[27];
    const float* w2    = (const float*)d_in[28];
    const float* w3    = (const float*)d_in[29];
    float* out = (float*)d_out;

    float *p_ln, *p_q, *p_k, *p_v, *p_s, *p_ctx, *p_res, *p_t1, *p_t3, *p_pout;
    cudaGetSymbolAddress((void**)&p_ln,   g_ln);
    cudaGetSymbolAddress((void**)&p_q,    g_q);
    cudaGetSymbolAddress((void**)&p_k,    g_k);
    cudaGetSymbolAddress((void**)&p_v,    g_v);
    cudaGetSymbolAddress((void**)&p_s,    g_sc);
    cudaGetSymbolAddress((void**)&p_ctx,  g_ctx);
    cudaGetSymbolAddress((void**)&p_res,  g_res);
    cudaGetSymbolAddress((void**)&p_t1,   g_t1);
    cudaGetSymbolAddress((void**)&p_t3,   g_t3);
    cudaGetSymbolAddress((void**)&p_pout, g_pout);

    const int M = Bc*Sc;       // 1024
    const int ME = Bc*SKc;     // 2048

    k_route<<<1, 32>>>(langs);

    // ===== self attention (causal GQA) =====
    k_ln<<<M, 256>>>(hid, ln1g, ln1b, p_ln);
    k_gemm<<<dim3(Dc/128,   M/128), 256>>>(p_ln, saqw, p_q, M, Dc,   Dc, saqb, nullptr, QSCALE, 2);
    k_gemm<<<dim3(KVDc/128, M/128), 256>>>(p_ln, sakw, p_k, M, KVDc, Dc, sakb, nullptr, 1.f, 1);
    k_gemm<<<dim3(KVDc/128, M/128), 256>>>(p_ln, savw, p_v, M, KVDc, Dc, savb, nullptr, 1.f, 1);
    k_scores<<<dim3(Sc/64, Sc/64, Bc*NHc), 256>>>(p_q, p_k, amask, p_s, Sc);
    k_softmax<<<(Bc*NHc*Sc)/8, 256>>>(p_s, Sc);
    k_pv<<<dim3(Sc/64, 1, Bc*NHc), 256>>>(p_s, p_v, p_ctx, Sc);
    k_gemm<<<dim3(Dc/128, M/128), 256>>>(p_ctx, saow, p_res, M, Dc, Dc, saob, hid, 1.f, 3);

    // ===== cross attention over encoder states =====
    k_ln<<<M, 256>>>(p_res, ln2g, ln2b, p_ln);
    k_gemm<<<dim3(Dc/128,   M/128),  256>>>(p_ln, caqw, p_q, M,  Dc,   Dc, caqb, nullptr, QSCALE, 2);
    k_gemm<<<dim3(KVDc/128, ME/128), 256>>>(enc,  cakw, p_k, ME, KVDc, Dc, cakb, nullptr, 1.f, 1);
    k_gemm<<<dim3(KVDc/128, ME/128), 256>>>(enc,  cavw, p_v, ME, KVDc, Dc, cavb, nullptr, 1.f, 1);
    k_scores<<<dim3(Sc/64, SKc/64, Bc*NHc), 256>>>(p_q, p_k, emask, p_s, SKc);
    k_softmax<<<(Bc*NHc*Sc)/8, 256>>>(p_s, SKc);
    k_pv<<<dim3(Sc/64, 1, Bc*NHc), 256>>>(p_s, p_v, p_ctx, SKc);
    k_gemm<<<dim3(Dc/128, M/128), 256>>>(p_ctx, caow, p_res, M, Dc, Dc, caob, p_res, 1.f, 3);

    // ===== language-routed MoE FFN =====
    k_ln<<<M, 256>>>(p_res, ln3g, ln3b, p_ln);
    k_moe_up<<<dim3(DEc/128, Sc/128, NEc*Bc), 256>>>(p_ln, w1, p_t1);
    k_moe_up<<<dim3(DEc/128, Sc/128, NEc*Bc), 256>>>(p_ln, w3, p_t3);
    k_moe_act<<<dim3((Sc*DEc)/1024, NEc*Bc), 256>>>(p_t1, p_t3);
    k_moe_down<<<dim3(Dc/128, Sc/128, NEc*Bc), 256>>>(p_t1, w2, p_pout);
    k_final<<<(Bc*Sc*Dc)/256, 256>>>(p_res, p_pout, out);
}

// round 8
// speedup vs baseline: 3.0786x; 3.0786x over previous
#include <cuda_runtime.h>
#include <cuda_bf16.h>
#include <math.h>

// ---------------- problem constants ----------------
#define Bc   4
#define Sc   256
#define SKc  512
#define Dc   1024
#define NHc  16
#define NKVc 4
#define HDc  64
#define KVDc (NKVc*HDc)   // 256
#define DEc  4096
#define NEc  8
#define LN_EPS 1e-5f
#define QSCALE 0.125f     // HD^-0.5

// ---------------- scratch (device globals; no allocs allowed) ----------------
__device__ float g_ln  [Bc*Sc*Dc];
__device__ float g_q   [Bc*Sc*Dc];
__device__ float g_k   [Bc*SKc*KVDc];
__device__ float g_v   [Bc*SKc*KVDc];
__device__ float g_sc  [(size_t)Bc*NHc*Sc*SKc];
__device__ float g_ctx [Bc*Sc*Dc];
__device__ float g_res [Bc*Sc*Dc];
__device__ float g_t1  [(size_t)NEc*Bc*Sc*DEc];
__device__ float g_t3  [(size_t)NEc*Bc*Sc*DEc];
__device__ float g_pout[(size_t)NEc*Bc*Sc*Dc];
__device__ float g_coef[NEc*Bc];

// ---------------- routing ----------------
__global__ void k_route(const int* __restrict__ langs) {
    if (threadIdx.x == 0 && blockIdx.x == 0) {
        for (int b = 0; b < Bc; b++) {
            int l0 = langs[2*b], l1 = langs[2*b+1];
            int cnt = (l0 > 3) + (l1 > 3);
            float rw = (cnt == 0) ? 1.f : 1.f / (float)cnt;
            for (int e = 0; e < NEc; e++) {
                int code = 4 + e;
                g_coef[e*Bc + b] = ((l0 == code) || (l1 == code)) ? rw : 0.f;
            }
        }
    }
}

// ---------------- layernorm (block per row) ----------------
__global__ void k_ln(const float* __restrict__ x, const float* __restrict__ g,
                     const float* __restrict__ bta, float* __restrict__ y) {
    int row = blockIdx.x;
    int tid = threadIdx.x;
    const float* xr = x + (size_t)row * Dc;
    float s = 0.f, s2 = 0.f;
    for (int i = tid; i < Dc; i += 256) { float v = xr[i]; s += v; s2 += v*v; }
    __shared__ float r1[256], r2[256];
    r1[tid] = s; r2[tid] = s2; __syncthreads();
    for (int off = 128; off > 0; off >>= 1) {
        if (tid < off) { r1[tid] += r1[tid+off]; r2[tid] += r2[tid+off]; }
        __syncthreads();
    }
    float mean = r1[0] * (1.f/Dc);
    float var  = r2[0] * (1.f/Dc) - mean*mean;
    float inv  = rsqrtf(var + LN_EPS);
    for (int i = tid; i < Dc; i += 256)
        y[(size_t)row*Dc + i] = (xr[i] - mean) * inv * g[i] + bta[i];
}

// ---------------- tf32 mma.sync GEMM: 128x128 tile, double-buffered ----------------
__device__ __forceinline__ unsigned f2tf(float f) {
    unsigned u; asm("cvt.rna.tf32.f32 %0, %1;" : "=r"(u) : "f"(f)); return u;
}

__device__ __forceinline__ void mma_tf32(float* d, const unsigned* a, const unsigned* b) {
    asm volatile(
        "mma.sync.aligned.m16n8k8.row.col.f32.tf32.tf32.f32 "
        "{%0,%1,%2,%3}, {%4,%5,%6,%7}, {%8,%9}, {%0,%1,%2,%3};\n"
        : "+f"(d[0]), "+f"(d[1]), "+f"(d[2]), "+f"(d[3])
        : "r"(a[0]), "r"(a[1]), "r"(a[2]), "r"(a[3]), "r"(b[0]), "r"(b[1]));
}

#define PADk 136

// mode: 0 = plain, 1 = +bias, 2 = (+bias)*scale, 3 = +bias+res
__device__ __forceinline__ void mma_tile(
    const float* __restrict__ A, const float* __restrict__ Bm, float* __restrict__ C,
    int M, int N, int K,
    const float* __restrict__ bias, const float* __restrict__ res,
    float scale, int mode)
{
    __shared__ unsigned As[2][16][PADk];
    __shared__ unsigned Bs[2][16][PADk];

    int tid  = threadIdx.x;
    int wid  = tid >> 5, lane = tid & 31;
    int g    = lane >> 2, tg = lane & 3;
    int wm   = (wid >> 2) * 64;   // 0 or 64
    int wn   = (wid & 3) * 32;    // 0,32,64,96
    int bm   = blockIdx.y * 128;
    int bn   = blockIdx.x * 128;

    float acc[4][4][4];
    #pragma unroll
    for (int i = 0; i < 4; i++)
        #pragma unroll
        for (int j = 0; j < 4; j++)
            #pragma unroll
            for (int q = 0; q < 4; q++) acc[i][j][q] = 0.f;

    // global-load coordinates
    int arow = tid >> 2;            // 0..63  (and +64)
    int acol = (tid & 3) * 4;       // 0,4,8,12
    int brow = tid >> 5;            // 0..7   (and +8)
    int bcol = (tid & 31) * 4;      // 0..124

    const float* Agp = A + (size_t)(bm + arow) * K + acol;
    const float* Agq = A + (size_t)(bm + arow + 64) * K + acol;
    const float* Bgp = Bm + (size_t)brow * N + bn + bcol;
    const float* Bgq = Bm + (size_t)(brow + 8) * N + bn + bcol;

    float4 pa0, pa1, pb0, pb1;

    auto ld_stage = [&](int k0) {
        pa0 = *reinterpret_cast<const float4*>(Agp + k0);
        pa1 = *reinterpret_cast<const float4*>(Agq + k0);
        pb0 = *reinterpret_cast<const float4*>(Bgp + (size_t)k0 * N);
        pb1 = *reinterpret_cast<const float4*>(Bgq + (size_t)k0 * N);
    };
    auto st_stage = [&](int buf) {
        As[buf][acol+0][arow] = f2tf(pa0.x);
        As[buf][acol+1][arow] = f2tf(pa0.y);
        As[buf][acol+2][arow] = f2tf(pa0.z);
        As[buf][acol+3][arow] = f2tf(pa0.w);
        As[buf][acol+0][arow+64] = f2tf(pa1.x);
        As[buf][acol+1][arow+64] = f2tf(pa1.y);
        As[buf][acol+2][arow+64] = f2tf(pa1.z);
        As[buf][acol+3][arow+64] = f2tf(pa1.w);
        uint4 t0; t0.x=f2tf(pb0.x); t0.y=f2tf(pb0.y); t0.z=f2tf(pb0.z); t0.w=f2tf(pb0.w);
        *reinterpret_cast<uint4*>(&Bs[buf][brow][bcol]) = t0;
        uint4 t1; t1.x=f2tf(pb1.x); t1.y=f2tf(pb1.y); t1.z=f2tf(pb1.z); t1.w=f2tf(pb1.w);
        *reinterpret_cast<uint4*>(&Bs[buf][brow+8][bcol]) = t1;
    };

    ld_stage(0);
    st_stage(0);
    __syncthreads();

    int buf = 0;
    for (int k0 = 0; k0 < K; k0 += 16) {
        bool more = (k0 + 16) < K;
        if (more) ld_stage(k0 + 16);

        #pragma unroll
        for (int ks = 0; ks < 2; ks++) {
            int kb = ks * 8;
            unsigned af[4][4], bf[4][2];
            #pragma unroll
            for (int mt = 0; mt < 4; mt++) {
                int m0 = wm + mt*16;
                af[mt][0] = As[buf][kb+tg  ][m0+g];
                af[mt][1] = As[buf][kb+tg  ][m0+g+8];
                af[mt][2] = As[buf][kb+tg+4][m0+g];
                af[mt][3] = As[buf][kb+tg+4][m0+g+8];
            }
            #pragma unroll
            for (int nt = 0; nt < 4; nt++) {
                int n0 = wn + nt*8 + g;
                bf[nt][0] = Bs[buf][kb+tg  ][n0];
                bf[nt][1] = Bs[buf][kb+tg+4][n0];
            }
            #pragma unroll
            for (int mt = 0; mt < 4; mt++)
                #pragma unroll
                for (int nt = 0; nt < 4; nt++)
                    mma_tf32(acc[mt][nt], af[mt], bf[nt]);
        }

        if (more) {
            st_stage(buf ^ 1);
            __syncthreads();
            buf ^= 1;
        }
    }

    // epilogue
    #pragma unroll
    for (int mt = 0; mt < 4; mt++) {
        int r0 = bm + wm + mt*16 + g;
        int r1 = r0 + 8;
        #pragma unroll
        for (int nt = 0; nt < 4; nt++) {
            int c = bn + wn + nt*8 + 2*tg;
            float v00 = acc[mt][nt][0], v01 = acc[mt][nt][1];
            float v10 = acc[mt][nt][2], v11 = acc[mt][nt][3];
            if (mode == 1) {
                float b0 = bias[c], b1 = bias[c+1];
                v00 += b0; v01 += b1; v10 += b0; v11 += b1;
            } else if (mode == 2) {
                float b0 = bias[c], b1 = bias[c+1];
                v00 = (v00+b0)*scale; v01 = (v01+b1)*scale;
                v10 = (v10+b0)*scale; v11 = (v11+b1)*scale;
            } else if (mode == 3) {
                float b0 = bias[c], b1 = bias[c+1];
                float2 x0 = *reinterpret_cast<const float2*>(res + (size_t)r0*N + c);
                float2 x1 = *reinterpret_cast<const float2*>(res + (size_t)r1*N + c);
                v00 += b0 + x0.x; v01 += b1 + x0.y;
                v10 += b0 + x1.x; v11 += b1 + x1.y;
            }
            float2 o0; o0.x = v00; o0.y = v01;
            float2 o1; o1.x = v10; o1.y = v11;
            *reinterpret_cast<float2*>(C + (size_t)r0*N + c) = o0;
            *reinterpret_cast<float2*>(C + (size_t)r1*N + c) = o1;
        }
    }
}

__global__ void __launch_bounds__(256)
k_gemm(const float* __restrict__ A, const float* __restrict__ B,
       float* __restrict__ C, int M, int N, int K,
       const float* __restrict__ bias, const float* __restrict__ res,
       float scale, int mode)
{
    mma_tile(A, B, C, M, N, K, bias, res, scale, mode);
}

// ---------------- attention: scores = Q K^T + mask ----------------
__global__ void k_scores(const float* __restrict__ q, const float* __restrict__ kmat,
                         const float* __restrict__ mask, float* __restrict__ out, int Skv)
{
    int z = blockIdx.z;
    int b = z / NHc, h = z % NHc, kvh = h >> 2;
    int q0 = blockIdx.x * 64, k0 = blockIdx.y * 64;
    __shared__ float Qs[64][65];
    __shared__ float Ks[64][65];
    int tid = threadIdx.x;

    for (int t = tid; t < 1024; t += 256) {
        int r = t >> 4, c = (t & 15) << 2;
        float4 v = *reinterpret_cast<const float4*>(
            q + (size_t)(b*Sc + q0 + r)*Dc + h*HDc + c);
        Qs[r][c] = v.x; Qs[r][c+1] = v.y; Qs[r][c+2] = v.z; Qs[r][c+3] = v.w;
        float4 w = *reinterpret_cast<const float4*>(
            kmat + (size_t)(b*Skv + k0 + r)*KVDc + kvh*HDc + c);
        Ks[r][c] = w.x; Ks[r][c+1] = w.y; Ks[r][c+2] = w.z; Ks[r][c+3] = w.w;
    }
    __syncthreads();

    int tx = tid & 15, ty = tid >> 4;
    float acc[4][4];
    #pragma unroll
    for (int i = 0; i < 4; i++)
        #pragma unroll
        for (int j = 0; j < 4; j++) acc[i][j] = 0.f;

    #pragma unroll 8
    for (int kk = 0; kk < 64; kk++) {
        float a[4], bb[4];
        #pragma unroll
        for (int i = 0; i < 4; i++) a[i]  = Qs[ty*4 + i][kk];
        #pragma unroll
        for (int j = 0; j < 4; j++) bb[j] = Ks[tx*4 + j][kk];
        #pragma unroll
        for (int i = 0; i < 4; i++)
            #pragma unroll
            for (int j = 0; j < 4; j++) acc[i][j] += a[i] * bb[j];
    }
    #pragma unroll
    for (int i = 0; i < 4; i++) {
        int qr = q0 + ty*4 + i;
        #pragma unroll
        for (int j = 0; j < 4; j++) {
            int kc = k0 + tx*4 + j;
            out[((size_t)z*Sc + qr)*Skv + kc] =
                acc[i][j] + mask[((size_t)b*Sc + qr)*Skv + kc];
        }
    }
}

// ---------------- row softmax (warp per row) ----------------
__global__ void k_softmax(float* __restrict__ s, int L) {
    int row  = blockIdx.x * 8 + (threadIdx.x >> 5);
    int lane = threadIdx.x & 31;
    float* p = s + (size_t)row * L;
    float m = -3.4e38f;
    for (int i = lane; i < L; i += 32) m = fmaxf(m, p[i]);
    #pragma unroll
    for (int off = 16; off > 0; off >>= 1) m = fmaxf(m, __shfl_xor_sync(0xffffffffu, m, off));
    float sum = 0.f;
    for (int i = lane; i < L; i += 32) { float e = __expf(p[i] - m); p[i] = e; sum += e; }
    #pragma unroll
    for (int off = 16; off > 0; off >>= 1) sum += __shfl_xor_sync(0xffffffffu, sum, off);
    float inv = 1.f / sum;
    for (int i = lane; i < L; i += 32) p[i] *= inv;
}

// ---------------- attention: ctx = P V ----------------
__global__ void k_pv(const float* __restrict__ sm, const float* __restrict__ v,
                     float* __restrict__ ctx, int Skv)
{
    int z = blockIdx.z;
    int b = z / NHc, h = z % NHc, kvh = h >> 2;
    int q0 = blockIdx.x * 64;
    __shared__ float Ps[64][65];
    __shared__ float Vs[64][65];
    int tid = threadIdx.x;
    int tx = tid & 15, ty = tid >> 4;

    float acc[4][4];
    #pragma unroll
    for (int i = 0; i < 4; i++)
        #pragma unroll
        for (int j = 0; j < 4; j++) acc[i][j] = 0.f;

    for (int kc = 0; kc < Skv; kc += 64) {
        for (int t = tid; t < 1024; t += 256) {
            int r = t >> 4, c = (t & 15) << 2;
            float4 pv = *reinterpret_cast<const float4*>(
                sm + ((size_t)z*Sc + q0 + r)*Skv + kc + c);
            Ps[r][c] = pv.x; Ps[r][c+1] = pv.y; Ps[r][c+2] = pv.z; Ps[r][c+3] = pv.w;
            float4 vv = *reinterpret_cast<const float4*>(
                v + (size_t)(b*Skv + kc + r)*KVDc + kvh*HDc + c);
            Vs[r][c] = vv.x; Vs[r][c+1] = vv.y; Vs[r][c+2] = vv.z; Vs[r][c+3] = vv.w;
        }
        __syncthreads();
        #pragma unroll 8
        for (int kk = 0; kk < 64; kk++) {
            float a[4], bb[4];
            #pragma unroll
            for (int i = 0; i < 4; i++) a[i]  = Ps[ty*4 + i][kk];
            #pragma unroll
            for (int j = 0; j < 4; j++) bb[j] = Vs[kk][tx*4 + j];
            #pragma unroll
            for (int i = 0; i < 4; i++)
                #pragma unroll
                for (int j = 0; j < 4; j++) acc[i][j] += a[i] * bb[j];
        }
        __syncthreads();
    }
    #pragma unroll
    for (int i = 0; i < 4; i++) {
        int qr = q0 + ty*4 + i;
        #pragma unroll
        for (int j = 0; j < 4; j++)
            ctx[(size_t)(b*Sc + qr)*Dc + h*HDc + tx*4 + j] = acc[i][j];
    }
}

// ---------------- MoE GEMMs (early-exit on coef==0) ----------------
__global__ void __launch_bounds__(256)
k_moe_up(const float* __restrict__ x, const float* __restrict__ W,
         float* __restrict__ out)
{
    int p = blockIdx.z;
    if (g_coef[p] == 0.f) return;
    int e = p / Bc, b = p % Bc;
    mma_tile(x + (size_t)b*Sc*Dc, W + (size_t)e*Dc*DEc, out + (size_t)p*Sc*DEc,
             Sc, DEc, Dc, nullptr, nullptr, 1.f, 0);
}

__global__ void __launch_bounds__(256)
k_moe_down(const float* __restrict__ h, const float* __restrict__ W,
           float* __restrict__ out)
{
    int p = blockIdx.z;
    if (g_coef[p] == 0.f) return;
    int e = p / Bc;
    mma_tile(h + (size_t)p*Sc*DEc, W + (size_t)e*DEc*Dc, out + (size_t)p*Sc*Dc,
             Sc, Dc, DEc, nullptr, nullptr, 1.f, 0);
}

__device__ __forceinline__ float gelu_exact(float x) {
    return 0.5f * x * (1.f + erff(x * 0.70710678118654752f));
}

__global__ void k_moe_act(float* __restrict__ t1, const float* __restrict__ t3) {
    int p = blockIdx.y;
    if (g_coef[p] == 0.f) return;
    size_t base = (size_t)p*Sc*DEc + ((size_t)blockIdx.x*256 + threadIdx.x)*4;
    float4 a = *reinterpret_cast<float4*>(t1 + base);
    float4 c = *reinterpret_cast<const float4*>(t3 + base);
    a.x = gelu_exact(a.x) * c.x;
    a.y = gelu_exact(a.y) * c.y;
    a.z = gelu_exact(a.z) * c.z;
    a.w = gelu_exact(a.w) * c.w;
    *reinterpret_cast<float4*>(t1 + base) = a;
}

__global__ void k_final(const float* __restrict__ res, const float* __restrict__ pout,
                        float* __restrict__ out)
{
    int idx = blockIdx.x * 256 + threadIdx.x;
    int b   = idx / (Sc*Dc);
    int off = idx - b*(Sc*Dc);
    float v = res[idx];
    #pragma unroll
    for (int e = 0; e < NEc; e++) {
        float cf = g_coef[e*Bc + b];
        if (cf != 0.f) v += cf * pout[(size_t)(e*Bc + b)*Sc*Dc + off];
    }
    out[idx] = v;
}

// ---------------- launch ----------------
extern "C" void kernel_launch(void* const* d_in, const int* in_sizes, int n_in,
                              void* d_out, int out_size)
{
    (void)in_sizes; (void)n_in; (void)out_size;
    const float* hid   = (const float*)d_in[0];
    const float* enc   = (const float*)d_in[1];
    const float* amask = (const float*)d_in[2];
    const float* emask = (const float*)d_in[3];
    const int*   langs = (const int*)  d_in[4];
    const float* ln1g  = (const float*)d_in[5];
    const float* ln1b  = (const float*)d_in[6];
    const float* saqw  = (const float*)d_in[7];
    const float* saqb  = (const float*)d_in[8];
    const float* sakw  = (const float*)d_in[9];
    const float* sakb  = (const float*)d_in[10];
    const float* savw  = (const float*)d_in[11];
    const float* savb  = (const float*)d_in[12];
    const float* saow  = (const float*)d_in[13];
    const float* saob  = (const float*)d_in[14];
    const float* ln2g  = (const float*)d_in[15];
    const float* ln2b  = (const float*)d_in[16];
    const float* caqw  = (const float*)d_in[17];
    const float* caqb  = (const float*)d_in[18];
    const float* cakw  = (const float*)d_in[19];
    const float* cakb  = (const float*)d_in[20];
    const float* cavw  = (const float*)d_in[21];
    const float* cavb  = (const float*)d_in[22];
    const float* caow  = (const float*)d_in[23];
    const float* caob  = (const float*)d_in[24];
    const float* ln3g  = (const float*)d_in[25];
    const float* ln3b  = (const float*)d_in[26];
    const float* w1    = (const float*)d_in[27];
    const float* w2    = (const float*)d_in[28];
    const float* w3    = (const float*)d_in[29];
    float* out = (float*)d_out;

    float *p_ln, *p_q, *p_k, *p_v, *p_s, *p_ctx, *p_res, *p_t1, *p_t3, *p_pout;
    cudaGetSymbolAddress((void**)&p_ln,   g_ln);
    cudaGetSymbolAddress((void**)&p_q,    g_q);
    cudaGetSymbolAddress((void**)&p_k,    g_k);
    cudaGetSymbolAddress((void**)&p_v,    g_v);
    cudaGetSymbolAddress((void**)&p_s,    g_sc);
    cudaGetSymbolAddress((void**)&p_ctx,  g_ctx);
    cudaGetSymbolAddress((void**)&p_res,  g_res);
    cudaGetSymbolAddress((void**)&p_t1,   g_t1);
    cudaGetSymbolAddress((void**)&p_t3,   g_t3);
    cudaGetSymbolAddress((void**)&p_pout, g_pout);

    const int M = Bc*Sc;       // 1024
    const int ME = Bc*SKc;     // 2048

    k_route<<<1, 32>>>(langs);

    // ===== self attention (causal GQA) =====
    k_ln<<<M, 256>>>(hid, ln1g, ln1b, p_ln);
    k_gemm<<<dim3(Dc/128,   M/128), 256>>>(p_ln, saqw, p_q, M, Dc,   Dc, saqb, nullptr, QSCALE, 2);
    k_gemm<<<dim3(KVDc/128, M/128), 256>>>(p_ln, sakw, p_k, M, KVDc, Dc, sakb, nullptr, 1.f, 1);
    k_gemm<<<dim3(KVDc/128, M/128), 256>>>(p_ln, savw, p_v, M, KVDc, Dc, savb, nullptr, 1.f, 1);
    k_scores<<<dim3(Sc/64, Sc/64, Bc*NHc), 256>>>(p_q, p_k, amask, p_s, Sc);
    k_softmax<<<(Bc*NHc*Sc)/8, 256>>>(p_s, Sc);
    k_pv<<<dim3(Sc/64, 1, Bc*NHc), 256>>>(p_s, p_v, p_ctx, Sc);
    k_gemm<<<dim3(Dc/128, M/128), 256>>>(p_ctx, saow, p_res, M, Dc, Dc, saob, hid, 1.f, 3);

    // ===== cross attention over encoder states =====
    k_ln<<<M, 256>>>(p_res, ln2g, ln2b, p_ln);
    k_gemm<<<dim3(Dc/128,   M/128),  256>>>(p_ln, caqw, p_q, M,  Dc,   Dc, caqb, nullptr, QSCALE, 2);
    k_gemm<<<dim3(KVDc/128, ME/128), 256>>>(enc,  cakw, p_k, ME, KVDc, Dc, cakb, nullptr, 1.f, 1);
    k_gemm<<<dim3(KVDc/128, ME/128), 256>>>(enc,  cavw, p_v, ME, KVDc, Dc, cavb, nullptr, 1.f, 1);
    k_scores<<<dim3(Sc/64, SKc/64, Bc*NHc), 256>>>(p_q, p_k, emask, p_s, SKc);
    k_softmax<<<(Bc*NHc*Sc)/8, 256>>>(p_s, SKc);
    k_pv<<<dim3(Sc/64, 1, Bc*NHc), 256>>>(p_s, p_v, p_ctx, SKc);
    k_gemm<<<dim3(Dc/128, M/128), 256>>>(p_ctx, caow, p_res, M, Dc, Dc, caob, p_res, 1.f, 3);

    // ===== language-routed MoE FFN =====
    k_ln<<<M, 256>>>(p_res, ln3g, ln3b, p_ln);
    k_moe_up<<<dim3(DEc/128, Sc/128, NEc*Bc), 256>>>(p_ln, w1, p_t1);
    k_moe_up<<<dim3(DEc/128, Sc/128, NEc*Bc), 256>>>(p_ln, w3, p_t3);
    k_moe_act<<<dim3((Sc*DEc)/1024, NEc*Bc), 256>>>(p_t1, p_t3);
    k_moe_down<<<dim3(Dc/128, Sc/128, NEc*Bc), 256>>>(p_t1, w2, p_pout);
    k_final<<<(Bc*Sc*Dc)/256, 256>>>(p_res, p_pout, out);
}

// round 9
// speedup vs baseline: 4.2631x; 1.3848x over previous
#include <cuda_runtime.h>
#include <cuda_bf16.h>
#include <math.h>

// ---------------- problem constants ----------------
#define Bc   4
#define Sc   256
#define SKc  512
#define Dc   1024
#define NHc  16
#define NKVc 4
#define HDc  64
#define KVDc (NKVc*HDc)   // 256
#define DEc  4096
#define NEc  8
#define LN_EPS 1e-5f
#define QSCALE 0.125f     // HD^-0.5

// ---------------- scratch (device globals; no allocs allowed) ----------------
__device__ float g_ln  [Bc*Sc*Dc];
__device__ float g_q   [Bc*Sc*Dc];
__device__ float g_k   [Bc*SKc*KVDc];
__device__ float g_v   [Bc*SKc*KVDc];
__device__ float g_sc  [(size_t)Bc*NHc*Sc*SKc];
__device__ float g_ctx [Bc*Sc*Dc];
__device__ float g_res [Bc*Sc*Dc];
__device__ float g_t1  [(size_t)NEc*Bc*Sc*DEc];
__device__ float g_t3  [(size_t)NEc*Bc*Sc*DEc];
__device__ float g_pout[(size_t)NEc*Bc*Sc*Dc];
__device__ float g_coef[NEc*Bc];

// ---------------- routing ----------------
__global__ void k_route(const int* __restrict__ langs) {
    if (threadIdx.x == 0 && blockIdx.x == 0) {
        for (int b = 0; b < Bc; b++) {
            int l0 = langs[2*b], l1 = langs[2*b+1];
            int cnt = (l0 > 3) + (l1 > 3);
            float rw = (cnt == 0) ? 1.f : 1.f / (float)cnt;
            for (int e = 0; e < NEc; e++) {
                int code = 4 + e;
                g_coef[e*Bc + b] = ((l0 == code) || (l1 == code)) ? rw : 0.f;
            }
        }
    }
}

// ---------------- layernorm (block per row) ----------------
__global__ void k_ln(const float* __restrict__ x, const float* __restrict__ g,
                     const float* __restrict__ bta, float* __restrict__ y) {
    int row = blockIdx.x;
    int tid = threadIdx.x;
    const float* xr = x + (size_t)row * Dc;
    float s = 0.f, s2 = 0.f;
    for (int i = tid; i < Dc; i += 256) { float v = xr[i]; s += v; s2 += v*v; }
    __shared__ float r1[256], r2[256];
    r1[tid] = s; r2[tid] = s2; __syncthreads();
    for (int off = 128; off > 0; off >>= 1) {
        if (tid < off) { r1[tid] += r1[tid+off]; r2[tid] += r2[tid+off]; }
        __syncthreads();
    }
    float mean = r1[0] * (1.f/Dc);
    float var  = r2[0] * (1.f/Dc) - mean*mean;
    float inv  = rsqrtf(var + LN_EPS);
    for (int i = tid; i < Dc; i += 256)
        y[(size_t)row*Dc + i] = (xr[i] - mean) * inv * g[i] + bta[i];
}

// ---------------- cp.async helpers ----------------
__device__ __forceinline__ void cp16(void* dst, const void* src) {
    unsigned sdst = (unsigned)__cvta_generic_to_shared(dst);
    asm volatile("cp.async.cg.shared.global [%0], [%1], 16;" :: "r"(sdst), "l"(src));
}
__device__ __forceinline__ void cp_commit() {
    asm volatile("cp.async.commit_group;");
}
template<int NN> __device__ __forceinline__ void cp_wait() {
    asm volatile("cp.async.wait_group %0;" :: "n"(NN));
}

__device__ __forceinline__ void mma_tf32(float* d, const unsigned* a, const unsigned* b) {
    asm volatile(
        "mma.sync.aligned.m16n8k8.row.col.f32.tf32.tf32.f32 "
        "{%0,%1,%2,%3}, {%4,%5,%6,%7}, {%8,%9}, {%0,%1,%2,%3};\n"
        : "+f"(d[0]), "+f"(d[1]), "+f"(d[2]), "+f"(d[3])
        : "r"(a[0]), "r"(a[1]), "r"(a[2]), "r"(a[3]), "r"(b[0]), "r"(b[1]));
}

// ---------------- templated tf32 MMA GEMM core (cp.async multi-stage) ----------------
// A row-major [M,K], B row-major [K,N], C row-major. fp32 in/out, tf32 HW truncation.
// mode: 0 = plain, 1 = +bias, 2 = (+bias)*scale, 3 = +bias+res
template<int BM, int BN, int WM, int WN, int STAGES>
__device__ __forceinline__ void mma_core(
    const float* __restrict__ A, const float* __restrict__ Bm, float* __restrict__ C,
    int N, int K,
    const float* __restrict__ bias, const float* __restrict__ res,
    float scale, int mode, int bm, int bn)
{
    constexpr int MT = WM/16, NT = WN/8;
    constexpr int APAD = 20;        // 16 + 4 (g*20+tg distinct mod 32)
    constexpr int BPAD = BN + 8;    // BPAD % 32 == 8 -> tg*8+g distinct
    constexpr int ACH = BM*4;       // float4 chunks per A stage
    constexpr int BCH = 16*(BN/4);
    constexpr int AIT = ACH/256;
    constexpr int BIT = BCH/256;

    __shared__ unsigned As[STAGES][BM][APAD];
    __shared__ unsigned Bs[STAGES][16][BPAD];

    int tid = threadIdx.x;
    int wid = tid >> 5, lane = tid & 31;
    int g = lane >> 2, tg = lane & 3;
    int wm = (wid >> 2) * WM;
    int wn = (wid & 3) * WN;

    float acc[MT][NT][4];
    #pragma unroll
    for (int i = 0; i < MT; i++)
        #pragma unroll
        for (int j = 0; j < NT; j++)
            #pragma unroll
            for (int q = 0; q < 4; q++) acc[i][j][q] = 0.f;

    auto issue = [&](int s, int k0) {
        #pragma unroll
        for (int i = 0; i < AIT; i++) {
            int c = tid + i*256;
            int row = c >> 2, cc = (c & 3) * 4;
            cp16(&As[s][row][cc], A + (size_t)(bm + row)*K + k0 + cc);
        }
        #pragma unroll
        for (int i = 0; i < BIT; i++) {
            int c = tid + i*256;
            int row = c / (BN/4), col = (c % (BN/4)) * 4;
            cp16(&Bs[s][row][col], Bm + (size_t)(k0 + row)*N + bn + col);
        }
    };

    const int NSTEPS = K / 16;
    #pragma unroll
    for (int s = 0; s < STAGES-1; s++) { issue(s, s*16); cp_commit(); }

    for (int k = 0; k < NSTEPS; k++) {
        cp_wait<STAGES-2>();
        __syncthreads();
        int ls = k + STAGES - 1;
        if (ls < NSTEPS) issue(ls % STAGES, ls * 16);
        cp_commit();

        int s = k % STAGES;
        #pragma unroll
        for (int ks = 0; ks < 2; ks++) {
            int kb = ks * 8;
            unsigned af[MT][4], bf[NT][2];
            #pragma unroll
            for (int mt = 0; mt < MT; mt++) {
                int m0 = wm + mt*16;
                af[mt][0] = As[s][m0 + g    ][kb + tg    ];
                af[mt][1] = As[s][m0 + g + 8][kb + tg    ];
                af[mt][2] = As[s][m0 + g    ][kb + tg + 4];
                af[mt][3] = As[s][m0 + g + 8][kb + tg + 4];
            }
            #pragma unroll
            for (int nt = 0; nt < NT; nt++) {
                int n0 = wn + nt*8 + g;
                bf[nt][0] = Bs[s][kb + tg    ][n0];
                bf[nt][1] = Bs[s][kb + tg + 4][n0];
            }
            #pragma unroll
            for (int mt = 0; mt < MT; mt++)
                #pragma unroll
                for (int nt = 0; nt < NT; nt++)
                    mma_tf32(acc[mt][nt], af[mt], bf[nt]);
        }
    }

    // epilogue
    #pragma unroll
    for (int mt = 0; mt < MT; mt++) {
        int r0 = bm + wm + mt*16 + g;
        int r1 = r0 + 8;
        #pragma unroll
        for (int nt = 0; nt < NT; nt++) {
            int c = bn + wn + nt*8 + 2*tg;
            float v00 = acc[mt][nt][0], v01 = acc[mt][nt][1];
            float v10 = acc[mt][nt][2], v11 = acc[mt][nt][3];
            if (mode == 1) {
                float b0 = bias[c], b1 = bias[c+1];
                v00 += b0; v01 += b1; v10 += b0; v11 += b1;
            } else if (mode == 2) {
                float b0 = bias[c], b1 = bias[c+1];
                v00 = (v00+b0)*scale; v01 = (v01+b1)*scale;
                v10 = (v10+b0)*scale; v11 = (v11+b1)*scale;
            } else if (mode == 3) {
                float b0 = bias[c], b1 = bias[c+1];
                float2 x0 = *reinterpret_cast<const float2*>(res + (size_t)r0*N + c);
                float2 x1 = *reinterpret_cast<const float2*>(res + (size_t)r1*N + c);
                v00 += b0 + x0.x; v01 += b1 + x0.y;
                v10 += b0 + x1.x; v11 += b1 + x1.y;
            }
            float2 o0; o0.x = v00; o0.y = v01;
            float2 o1; o1.x = v10; o1.y = v11;
            *reinterpret_cast<float2*>(C + (size_t)r0*N + c) = o0;
            *reinterpret_cast<float2*>(C + (size_t)r1*N + c) = o1;
        }
    }
}

// 64x64 tile, 4-stage: projections (big grids, latency-tolerant)
__global__ void __launch_bounds__(256)
k_gemm64(const float* __restrict__ A, const float* __restrict__ B,
         float* __restrict__ C, int N, int K,
         const float* __restrict__ bias, const float* __restrict__ res,
         float scale, int mode)
{
    mma_core<64,64,32,16,4>(A, B, C, N, K, bias, res, scale, mode,
                            blockIdx.y*64, blockIdx.x*64);
}

// fused K+V projection: z=0 -> K, z=1 -> V
__global__ void __launch_bounds__(256)
k_kv64(const float* __restrict__ A,
       const float* __restrict__ kw, const float* __restrict__ kb_,
       const float* __restrict__ vw, const float* __restrict__ vb_,
       float* __restrict__ outk, float* __restrict__ outv, int K)
{
    const float* W  = blockIdx.z ? vw : kw;
    const float* bi = blockIdx.z ? vb_ : kb_;
    float*       O  = blockIdx.z ? outv : outk;
    mma_core<64,64,32,16,4>(A, W, O, KVDc, K, bi, nullptr, 1.f, 1,
                            blockIdx.y*64, blockIdx.x*64);
}

// 128x128 tile, 2-stage: MoE (dense grids)
// fused w1/w3 up-projection: z = pair*2 + which
__global__ void __launch_bounds__(256)
k_moe_up(const float* __restrict__ x,
         const float* __restrict__ w1, const float* __restrict__ w3,
         float* __restrict__ t1, float* __restrict__ t3)
{
    int z = blockIdx.z;
    int p = z >> 1, which = z & 1;
    if (g_coef[p] == 0.f) return;
    int e = p / Bc, b = p % Bc;
    const float* W = which ? w3 : w1;
    float*       O = which ? t3 : t1;
    mma_core<128,128,64,32,2>(x + (size_t)b*Sc*Dc, W + (size_t)e*Dc*DEc,
                              O + (size_t)p*Sc*DEc, DEc, Dc,
                              nullptr, nullptr, 1.f, 0,
                              blockIdx.y*128, blockIdx.x*128);
}

__global__ void __launch_bounds__(256)
k_moe_down(const float* __restrict__ h, const float* __restrict__ W,
           float* __restrict__ out)
{
    int p = blockIdx.z;
    if (g_coef[p] == 0.f) return;
    int e = p / Bc;
    mma_core<128,128,64,32,2>(h + (size_t)p*Sc*DEc, W + (size_t)e*DEc*Dc,
                              out + (size_t)p*Sc*Dc, Dc, DEc,
                              nullptr, nullptr, 1.f, 0,
                              blockIdx.y*128, blockIdx.x*128);
}

// ---------------- attention: scores = Q K^T + mask ----------------
__global__ void k_scores(const float* __restrict__ q, const float* __restrict__ kmat,
                         const float* __restrict__ mask, float* __restrict__ out, int Skv)
{
    int z = blockIdx.z;
    int b = z / NHc, h = z % NHc, kvh = h >> 2;
    int q0 = blockIdx.x * 64, k0 = blockIdx.y * 64;
    __shared__ float Qs[64][65];
    __shared__ float Ks[64][65];
    int tid = threadIdx.x;

    for (int t = tid; t < 1024; t += 256) {
        int r = t >> 4, c = (t & 15) << 2;
        float4 v = *reinterpret_cast<const float4*>(
            q + (size_t)(b*Sc + q0 + r)*Dc + h*HDc + c);
        Qs[r][c] = v.x; Qs[r][c+1] = v.y; Qs[r][c+2] = v.z; Qs[r][c+3] = v.w;
        float4 w = *reinterpret_cast<const float4*>(
            kmat + (size_t)(b*Skv + k0 + r)*KVDc + kvh*HDc + c);
        Ks[r][c] = w.x; Ks[r][c+1] = w.y; Ks[r][c+2] = w.z; Ks[r][c+3] = w.w;
    }
    __syncthreads();

    int tx = tid & 15, ty = tid >> 4;
    float acc[4][4];
    #pragma unroll
    for (int i = 0; i < 4; i++)
        #pragma unroll
        for (int j = 0; j < 4; j++) acc[i][j] = 0.f;

    #pragma unroll 8
    for (int kk = 0; kk < 64; kk++) {
        float a[4], bb[4];
        #pragma unroll
        for (int i = 0; i < 4; i++) a[i]  = Qs[ty*4 + i][kk];
        #pragma unroll
        for (int j = 0; j < 4; j++) bb[j] = Ks[tx*4 + j][kk];
        #pragma unroll
        for (int i = 0; i < 4; i++)
            #pragma unroll
            for (int j = 0; j < 4; j++) acc[i][j] += a[i] * bb[j];
    }
    #pragma unroll
    for (int i = 0; i < 4; i++) {
        int qr = q0 + ty*4 + i;
        #pragma unroll
        for (int j = 0; j < 4; j++) {
            int kc = k0 + tx*4 + j;
            out[((size_t)z*Sc + qr)*Skv + kc] =
                acc[i][j] + mask[((size_t)b*Sc + qr)*Skv + kc];
        }
    }
}

// ---------------- row softmax (warp per row) ----------------
__global__ void k_softmax(float* __restrict__ s, int L) {
    int row  = blockIdx.x * 8 + (threadIdx.x >> 5);
    int lane = threadIdx.x & 31;
    float* p = s + (size_t)row * L;
    float m = -3.4e38f;
    for (int i = lane; i < L; i += 32) m = fmaxf(m, p[i]);
    #pragma unroll
    for (int off = 16; off > 0; off >>= 1) m = fmaxf(m, __shfl_xor_sync(0xffffffffu, m, off));
    float sum = 0.f;
    for (int i = lane; i < L; i += 32) { float e = __expf(p[i] - m); p[i] = e; sum += e; }
    #pragma unroll
    for (int off = 16; off > 0; off >>= 1) sum += __shfl_xor_sync(0xffffffffu, sum, off);
    float inv = 1.f / sum;
    for (int i = lane; i < L; i += 32) p[i] *= inv;
}

// ---------------- attention: ctx = P V ----------------
__global__ void k_pv(const float* __restrict__ sm, const float* __restrict__ v,
                     float* __restrict__ ctx, int Skv)
{
    int z = blockIdx.z;
    int b = z / NHc, h = z % NHc, kvh = h >> 2;
    int q0 = blockIdx.x * 64;
    __shared__ float Ps[64][65];
    __shared__ float Vs[64][65];
    int tid = threadIdx.x;
    int tx = tid & 15, ty = tid >> 4;

    float acc[4][4];
    #pragma unroll
    for (int i = 0; i < 4; i++)
        #pragma unroll
        for (int j = 0; j < 4; j++) acc[i][j] = 0.f;

    for (int kc = 0; kc < Skv; kc += 64) {
        for (int t = tid; t < 1024; t += 256) {
            int r = t >> 4, c = (t & 15) << 2;
            float4 pv = *reinterpret_cast<const float4*>(
                sm + ((size_t)z*Sc + q0 + r)*Skv + kc + c);
            Ps[r][c] = pv.x; Ps[r][c+1] = pv.y; Ps[r][c+2] = pv.z; Ps[r][c+3] = pv.w;
            float4 vv = *reinterpret_cast<const float4*>(
                v + (size_t)(b*Skv + kc + r)*KVDc + kvh*HDc + c);
            Vs[r][c] = vv.x; Vs[r][c+1] = vv.y; Vs[r][c+2] = vv.z; Vs[r][c+3] = vv.w;
        }
        __syncthreads();
        #pragma unroll 8
        for (int kk = 0; kk < 64; kk++) {
            float a[4], bb[4];
            #pragma unroll
            for (int i = 0; i < 4; i++) a[i]  = Ps[ty*4 + i][kk];
            #pragma unroll
            for (int j = 0; j < 4; j++) bb[j] = Vs[kk][tx*4 + j];
            #pragma unroll
            for (int i = 0; i < 4; i++)
                #pragma unroll
                for (int j = 0; j < 4; j++) acc[i][j] += a[i] * bb[j];
        }
        __syncthreads();
    }
    #pragma unroll
    for (int i = 0; i < 4; i++) {
        int qr = q0 + ty*4 + i;
        #pragma unroll
        for (int j = 0; j < 4; j++)
            ctx[(size_t)(b*Sc + qr)*Dc + h*HDc + tx*4 + j] = acc[i][j];
    }
}

// ---------------- MoE elementwise ----------------
__device__ __forceinline__ float gelu_exact(float x) {
    return 0.5f * x * (1.f + erff(x * 0.70710678118654752f));
}

__global__ void k_moe_act(float* __restrict__ t1, const float* __restrict__ t3) {
    int p = blockIdx.y;
    if (g_coef[p] == 0.f) return;
    size_t base = (size_t)p*Sc*DEc + ((size_t)blockIdx.x*256 + threadIdx.x)*4;
    float4 a = *reinterpret_cast<float4*>(t1 + base);
    float4 c = *reinterpret_cast<const float4*>(t3 + base);
    a.x = gelu_exact(a.x) * c.x;
    a.y = gelu_exact(a.y) * c.y;
    a.z = gelu_exact(a.z) * c.z;
    a.w = gelu_exact(a.w) * c.w;
    *reinterpret_cast<float4*>(t1 + base) = a;
}

__global__ void k_final(const float* __restrict__ res, const float* __restrict__ pout,
                        float* __restrict__ out)
{
    int idx = blockIdx.x * 256 + threadIdx.x;
    int b   = idx / (Sc*Dc);
    int off = idx - b*(Sc*Dc);
    float v = res[idx];
    #pragma unroll
    for (int e = 0; e < NEc; e++) {
        float cf = g_coef[e*Bc + b];
        if (cf != 0.f) v += cf * pout[(size_t)(e*Bc + b)*Sc*Dc + off];
    }
    out[idx] = v;
}

// ---------------- launch ----------------
extern "C" void kernel_launch(void* const* d_in, const int* in_sizes, int n_in,
                              void* d_out, int out_size)
{
    (void)in_sizes; (void)n_in; (void)out_size;
    const float* hid   = (const float*)d_in[0];
    const float* enc   = (const float*)d_in[1];
    const float* amask = (const float*)d_in[2];
    const float* emask = (const float*)d_in[3];
    const int*   langs = (const int*)  d_in[4];
    const float* ln1g  = (const float*)d_in[5];
    const float* ln1b  = (const float*)d_in[6];
    const float* saqw  = (const float*)d_in[7];
    const float* saqb  = (const float*)d_in[8];
    const float* sakw  = (const float*)d_in[9];
    const float* sakb  = (const float*)d_in[10];
    const float* savw  = (const float*)d_in[11];
    const float* savb  = (const float*)d_in[12];
    const float* saow  = (const float*)d_in[13];
    const float* saob  = (const float*)d_in[14];
    const float* ln2g  = (const float*)d_in[15];
    const float* ln2b  = (const float*)d_in[16];
    const float* caqw  = (const float*)d_in[17];
    const float* caqb  = (const float*)d_in[18];
    const float* cakw  = (const float*)d_in[19];
    const float* cakb  = (const float*)d_in[20];
    const float* cavw  = (const float*)d_in[21];
    const float* cavb  = (const float*)d_in[22];
    const float* caow  = (const float*)d_in[23];
    const float* caob  = (const float*)d_in[24];
    const float* ln3g  = (const float*)d_in[25];
    const float* ln3b  = (const float*)d_in[26];
    const float* w1    = (const float*)d_in[27];
    const float* w2    = (const float*)d_in[28];
    const float* w3    = (const float*)d_in[29];
    float* out = (float*)d_out;

    float *p_ln, *p_q, *p_k, *p_v, *p_s, *p_ctx, *p_res, *p_t1, *p_t3, *p_pout;
    cudaGetSymbolAddress((void**)&p_ln,   g_ln);
    cudaGetSymbolAddress((void**)&p_q,    g_q);
    cudaGetSymbolAddress((void**)&p_k,    g_k);
    cudaGetSymbolAddress((void**)&p_v,    g_v);
    cudaGetSymbolAddress((void**)&p_s,    g_sc);
    cudaGetSymbolAddress((void**)&p_ctx,  g_ctx);
    cudaGetSymbolAddress((void**)&p_res,  g_res);
    cudaGetSymbolAddress((void**)&p_t1,   g_t1);
    cudaGetSymbolAddress((void**)&p_t3,   g_t3);
    cudaGetSymbolAddress((void**)&p_pout, g_pout);

    const int M  = Bc*Sc;      // 1024
    const int ME = Bc*SKc;     // 2048

    k_route<<<1, 32>>>(langs);

    // ===== self attention (causal GQA) =====
    k_ln<<<M, 256>>>(hid, ln1g, ln1b, p_ln);
    k_gemm64<<<dim3(Dc/64, M/64), 256>>>(p_ln, saqw, p_q, Dc, Dc, saqb, nullptr, QSCALE, 2);
    k_kv64<<<dim3(KVDc/64, M/64, 2), 256>>>(p_ln, sakw, sakb, savw, savb, p_k, p_v, Dc);
    k_scores<<<dim3(Sc/64, Sc/64, Bc*NHc), 256>>>(p_q, p_k, amask, p_s, Sc);
    k_softmax<<<(Bc*NHc*Sc)/8, 256>>>(p_s, Sc);
    k_pv<<<dim3(Sc/64, 1, Bc*NHc), 256>>>(p_s, p_v, p_ctx, Sc);
    k_gemm64<<<dim3(Dc/64, M/64), 256>>>(p_ctx, saow, p_res, Dc, Dc, saob, hid, 1.f, 3);

    // ===== cross attention over encoder states =====
    k_ln<<<M, 256>>>(p_res, ln2g, ln2b, p_ln);
    k_gemm64<<<dim3(Dc/64, M/64), 256>>>(p_ln, caqw, p_q, Dc, Dc, caqb, nullptr, QSCALE, 2);
    k_kv64<<<dim3(KVDc/64, ME/64, 2), 256>>>(enc, cakw, cakb, cavw, cavb, p_k, p_v, Dc);
    k_scores<<<dim3(Sc/64, SKc/64, Bc*NHc), 256>>>(p_q, p_k, emask, p_s, SKc);
    k_softmax<<<(Bc*NHc*Sc)/8, 256>>>(p_s, SKc);
    k_pv<<<dim3(Sc/64, 1, Bc*NHc), 256>>>(p_s, p_v, p_ctx, SKc);
    k_gemm64<<<dim3(Dc/64, M/64), 256>>>(p_ctx, caow, p_res, Dc, Dc, caob, p_res, 1.f, 3);

    // ===== language-routed MoE FFN =====
    k_ln<<<M, 256>>>(p_res, ln3g, ln3b, p_ln);
    k_moe_up<<<dim3(DEc/128, Sc/128, NEc*Bc*2), 256>>>(p_ln, w1, w3, p_t1, p_t3);
    k_moe_act<<<dim3((Sc*DEc)/1024, NEc*Bc), 256>>>(p_t1, p_t3);
    k_moe_down<<<dim3(Dc/128, Sc/128, NEc*Bc), 256>>>(p_t1, w2, p_pout);
    k_final<<<(Bc*Sc*Dc)/256, 256>>>(p_res, p_pout, out);
}

// round 10
// speedup vs baseline: 4.9729x; 1.1665x over previous
#include <cuda_runtime.h>
#include <cuda_bf16.h>
#include <math.h>

// ---------------- problem constants ----------------
#define Bc   4
#define Sc   256
#define SKc  512
#define Dc   1024
#define NHc  16
#define NKVc 4
#define HDc  64
#define KVDc (NKVc*HDc)   // 256
#define DEc  4096
#define NEc  8
#define LN_EPS 1e-5f
#define QSCALE 0.125f     // HD^-0.5

// ---------------- scratch (device globals; no allocs allowed) ----------------
__device__ float g_ln  [Bc*Sc*Dc];
__device__ float g_q   [Bc*Sc*Dc];
__device__ float g_k   [Bc*SKc*KVDc];
__device__ float g_v   [Bc*SKc*KVDc];
__device__ float g_sc  [(size_t)Bc*NHc*Sc*SKc];
__device__ float g_ctx [Bc*Sc*Dc];
__device__ float g_res [Bc*Sc*Dc];
__device__ float g_t1  [(size_t)NEc*Bc*Sc*DEc];   // h = gelu(x@w1)*(x@w3)
__device__ float g_pout[(size_t)NEc*Bc*Sc*Dc];
__device__ float g_coef[NEc*Bc];

// ---------------- routing ----------------
__global__ void k_route(const int* __restrict__ langs) {
    if (threadIdx.x == 0 && blockIdx.x == 0) {
        for (int b = 0; b < Bc; b++) {
            int l0 = langs[2*b], l1 = langs[2*b+1];
            int cnt = (l0 > 3) + (l1 > 3);
            float rw = (cnt == 0) ? 1.f : 1.f / (float)cnt;
            for (int e = 0; e < NEc; e++) {
                int code = 4 + e;
                g_coef[e*Bc + b] = ((l0 == code) || (l1 == code)) ? rw : 0.f;
            }
        }
    }
}

// ---------------- layernorm (block per row) ----------------
__global__ void k_ln(const float* __restrict__ x, const float* __restrict__ g,
                     const float* __restrict__ bta, float* __restrict__ y) {
    int row = blockIdx.x;
    int tid = threadIdx.x;
    const float* xr = x + (size_t)row * Dc;
    float s = 0.f, s2 = 0.f;
    for (int i = tid; i < Dc; i += 256) { float v = xr[i]; s += v; s2 += v*v; }
    __shared__ float r1[256], r2[256];
    r1[tid] = s; r2[tid] = s2; __syncthreads();
    for (int off = 128; off > 0; off >>= 1) {
        if (tid < off) { r1[tid] += r1[tid+off]; r2[tid] += r2[tid+off]; }
        __syncthreads();
    }
    float mean = r1[0] * (1.f/Dc);
    float var  = r2[0] * (1.f/Dc) - mean*mean;
    float inv  = rsqrtf(var + LN_EPS);
    for (int i = tid; i < Dc; i += 256)
        y[(size_t)row*Dc + i] = (xr[i] - mean) * inv * g[i] + bta[i];
}

// ---------------- helpers ----------------
__device__ __forceinline__ void cp16(void* dst, const void* src) {
    unsigned sdst = (unsigned)__cvta_generic_to_shared(dst);
    asm volatile("cp.async.cg.shared.global [%0], [%1], 16;" :: "r"(sdst), "l"(src));
}
__device__ __forceinline__ void cp_commit() {
    asm volatile("cp.async.commit_group;");
}
template<int NN> __device__ __forceinline__ void cp_wait() {
    asm volatile("cp.async.wait_group %0;" :: "n"(NN));
}
__device__ __forceinline__ unsigned f2tf(float f) {
    unsigned u; asm("cvt.rna.tf32.f32 %0, %1;" : "=r"(u) : "f"(f)); return u;
}
__device__ __forceinline__ void mma_tf32(float* d, const unsigned* a, const unsigned* b) {
    asm volatile(
        "mma.sync.aligned.m16n8k8.row.col.f32.tf32.tf32.f32 "
        "{%0,%1,%2,%3}, {%4,%5,%6,%7}, {%8,%9}, {%0,%1,%2,%3};\n"
        : "+f"(d[0]), "+f"(d[1]), "+f"(d[2]), "+f"(d[3])
        : "r"(a[0]), "r"(a[1]), "r"(a[2]), "r"(a[3]), "r"(b[0]), "r"(b[1]));
}
__device__ __forceinline__ float gelu_exact(float x) {
    return 0.5f * x * (1.f + erff(x * 0.70710678118654752f));
}

// ---------------- templated tf32 MMA GEMM core (cp.async multi-stage) ----------------
// mode: 0 = plain, 1 = +bias, 2 = (+bias)*scale, 3 = +bias+res
template<int BM, int BN, int WM, int WN, int STAGES>
__device__ __forceinline__ void mma_core(
    const float* __restrict__ A, const float* __restrict__ Bm, float* __restrict__ C,
    int N, int K,
    const float* __restrict__ bias, const float* __restrict__ res,
    float scale, int mode, int bm, int bn)
{
    constexpr int MT = WM/16, NT = WN/8;
    constexpr int APAD = 20;
    constexpr int BPAD = BN + 8;
    constexpr int AIT = (BM*4)/256;
    constexpr int BIT = (16*(BN/4))/256;

    __shared__ unsigned As[STAGES][BM][APAD];
    __shared__ unsigned Bs[STAGES][16][BPAD];

    int tid = threadIdx.x;
    int wid = tid >> 5, lane = tid & 31;
    int g = lane >> 2, tg = lane & 3;
    int wm = (wid >> 2) * WM;
    int wn = (wid & 3) * WN;

    float acc[MT][NT][4];
    #pragma unroll
    for (int i = 0; i < MT; i++)
        #pragma unroll
        for (int j = 0; j < NT; j++)
            #pragma unroll
            for (int q = 0; q < 4; q++) acc[i][j][q] = 0.f;

    auto issue = [&](int s, int k0) {
        #pragma unroll
        for (int i = 0; i < AIT; i++) {
            int c = tid + i*256;
            int row = c >> 2, cc = (c & 3) * 4;
            cp16(&As[s][row][cc], A + (size_t)(bm + row)*K + k0 + cc);
        }
        #pragma unroll
        for (int i = 0; i < BIT; i++) {
            int c = tid + i*256;
            int row = c / (BN/4), col = (c % (BN/4)) * 4;
            cp16(&Bs[s][row][col], Bm + (size_t)(k0 + row)*N + bn + col);
        }
    };

    const int NSTEPS = K / 16;
    #pragma unroll
    for (int s = 0; s < STAGES-1; s++) { issue(s, s*16); cp_commit(); }

    for (int k = 0; k < NSTEPS; k++) {
        cp_wait<STAGES-2>();
        __syncthreads();
        int ls = k + STAGES - 1;
        if (ls < NSTEPS) issue(ls % STAGES, ls * 16);
        cp_commit();

        int s = k % STAGES;
        #pragma unroll
        for (int ks = 0; ks < 2; ks++) {
            int kb = ks * 8;
            unsigned af[MT][4], bf[NT][2];
            #pragma unroll
            for (int mt = 0; mt < MT; mt++) {
                int m0 = wm + mt*16;
                af[mt][0] = As[s][m0 + g    ][kb + tg    ];
                af[mt][1] = As[s][m0 + g + 8][kb + tg    ];
                af[mt][2] = As[s][m0 + g    ][kb + tg + 4];
                af[mt][3] = As[s][m0 + g + 8][kb + tg + 4];
            }
            #pragma unroll
            for (int nt = 0; nt < NT; nt++) {
                int n0 = wn + nt*8 + g;
                bf[nt][0] = Bs[s][kb + tg    ][n0];
                bf[nt][1] = Bs[s][kb + tg + 4][n0];
            }
            #pragma unroll
            for (int mt = 0; mt < MT; mt++)
                #pragma unroll
                for (int nt = 0; nt < NT; nt++)
                    mma_tf32(acc[mt][nt], af[mt], bf[nt]);
        }
    }

    #pragma unroll
    for (int mt = 0; mt < MT; mt++) {
        int r0 = bm + wm + mt*16 + g;
        int r1 = r0 + 8;
        #pragma unroll
        for (int nt = 0; nt < NT; nt++) {
            int c = bn + wn + nt*8 + 2*tg;
            float v00 = acc[mt][nt][0], v01 = acc[mt][nt][1];
            float v10 = acc[mt][nt][2], v11 = acc[mt][nt][3];
            if (mode == 1) {
                float b0 = bias[c], b1 = bias[c+1];
                v00 += b0; v01 += b1; v10 += b0; v11 += b1;
            } else if (mode == 2) {
                float b0 = bias[c], b1 = bias[c+1];
                v00 = (v00+b0)*scale; v01 = (v01+b1)*scale;
                v10 = (v10+b0)*scale; v11 = (v11+b1)*scale;
            } else if (mode == 3) {
                float b0 = bias[c], b1 = bias[c+1];
                float2 x0 = *reinterpret_cast<const float2*>(res + (size_t)r0*N + c);
                float2 x1 = *reinterpret_cast<const float2*>(res + (size_t)r1*N + c);
                v00 += b0 + x0.x; v01 += b1 + x0.y;
                v10 += b0 + x1.x; v11 += b1 + x1.y;
            }
            float2 o0; o0.x = v00; o0.y = v01;
            float2 o1; o1.x = v10; o1.y = v11;
            *reinterpret_cast<float2*>(C + (size_t)r0*N + c) = o0;
            *reinterpret_cast<float2*>(C + (size_t)r1*N + c) = o1;
        }
    }
}

// 64x64 tile, 4-stage: o-projection
__global__ void __launch_bounds__(256)
k_gemm64(const float* __restrict__ A, const float* __restrict__ B,
         float* __restrict__ C, int N, int K,
         const float* __restrict__ bias, const float* __restrict__ res,
         float scale, int mode)
{
    mma_core<64,64,32,16,4>(A, B, C, N, K, bias, res, scale, mode,
                            blockIdx.y*64, blockIdx.x*64);
}

// fused Q+K+V projections: 1D flattened grid.
// blocks: [0, MqB*16)           -> Q  (N=Dc, mode 2)
//         [nQ, nQ+MkvB*4)       -> K  (N=KVDc, mode 1)
//         [nQ+nKV, nQ+2*nKV)    -> V
__global__ void __launch_bounds__(256)
k_qkv(const float* __restrict__ Aq, int MqB, const float* __restrict__ Akv, int MkvB,
      const float* __restrict__ qw, const float* __restrict__ qb,
      const float* __restrict__ kw, const float* __restrict__ kb_,
      const float* __restrict__ vw, const float* __restrict__ vb_,
      float* __restrict__ oq, float* __restrict__ ok, float* __restrict__ ov)
{
    int id = blockIdx.x;
    int nQ = MqB * 16;
    int nKV = MkvB * 4;
    const float *A, *W, *bi; float* O;
    int N, mode, bm, bn; float sc = 1.f;
    if (id < nQ) {
        A = Aq; W = qw; bi = qb; O = oq; N = Dc; mode = 2; sc = QSCALE;
        bm = (id >> 4) * 64; bn = (id & 15) * 64;
    } else if (id < nQ + nKV) {
        int i2 = id - nQ;
        A = Akv; W = kw; bi = kb_; O = ok; N = KVDc; mode = 1;
        bm = (i2 >> 2) * 64; bn = (i2 & 3) * 64;
    } else {
        int i2 = id - nQ - nKV;
        A = Akv; W = vw; bi = vb_; O = ov; N = KVDc; mode = 1;
        bm = (i2 >> 2) * 64; bn = (i2 & 3) * 64;
    }
    mma_core<64,64,32,16,4>(A, W, O, N, Dc, bi, nullptr, sc, mode, bm, bn);
}

// ---------------- attention: scores = Q K^T + mask (tf32 mma) ----------------
// 64x64 tile per block over k=64. Q [m][k], K consumed [n][k] (natural layout).
__global__ void __launch_bounds__(256)
k_scores(const float* __restrict__ q, const float* __restrict__ kmat,
         const float* __restrict__ mask, float* __restrict__ out, int Skv)
{
    int z = blockIdx.z;
    int b = z / NHc, h = z % NHc, kvh = h >> 2;
    int q0 = blockIdx.x * 64, k0 = blockIdx.y * 64;
    __shared__ unsigned Qs[64][72];
    __shared__ unsigned Ks[64][72];
    int tid = threadIdx.x, lane = tid & 31, wid = tid >> 5;
    int g = lane >> 2, tg = lane & 3;
    int wm = (wid >> 2) * 32, wn = (wid & 3) * 16;

    #pragma unroll
    for (int i = 0; i < 4; i++) {
        int c = tid + i*256;
        int r = c >> 4, cc = (c & 15) << 2;
        float4 v = *reinterpret_cast<const float4*>(
            q + (size_t)(b*Sc + q0 + r)*Dc + h*HDc + cc);
        Qs[r][cc]=f2tf(v.x); Qs[r][cc+1]=f2tf(v.y); Qs[r][cc+2]=f2tf(v.z); Qs[r][cc+3]=f2tf(v.w);
        float4 w = *reinterpret_cast<const float4*>(
            kmat + (size_t)(b*Skv + k0 + r)*KVDc + kvh*HDc + cc);
        Ks[r][cc]=f2tf(w.x); Ks[r][cc+1]=f2tf(w.y); Ks[r][cc+2]=f2tf(w.z); Ks[r][cc+3]=f2tf(w.w);
    }
    __syncthreads();

    float acc[2][2][4];
    #pragma unroll
    for (int i = 0; i < 2; i++)
        #pragma unroll
        for (int j = 0; j < 2; j++)
            #pragma unroll
            for (int p = 0; p < 4; p++) acc[i][j][p] = 0.f;

    #pragma unroll
    for (int kb = 0; kb < 64; kb += 8) {
        unsigned af[2][4], bf[2][2];
        #pragma unroll
        for (int mt = 0; mt < 2; mt++) {
            int m0 = wm + mt*16;
            af[mt][0] = Qs[m0 + g    ][kb + tg    ];
            af[mt][1] = Qs[m0 + g + 8][kb + tg    ];
            af[mt][2] = Qs[m0 + g    ][kb + tg + 4];
            af[mt][3] = Qs[m0 + g + 8][kb + tg + 4];
        }
        #pragma unroll
        for (int nt = 0; nt < 2; nt++) {
            int n0 = wn + nt*8 + g;
            bf[nt][0] = Ks[n0][kb + tg    ];
            bf[nt][1] = Ks[n0][kb + tg + 4];
        }
        #pragma unroll
        for (int mt = 0; mt < 2; mt++)
            #pragma unroll
            for (int nt = 0; nt < 2; nt++)
                mma_tf32(acc[mt][nt], af[mt], bf[nt]);
    }

    #pragma unroll
    for (int mt = 0; mt < 2; mt++) {
        int qr0 = q0 + wm + mt*16 + g;
        int qr1 = qr0 + 8;
        #pragma unroll
        for (int nt = 0; nt < 2; nt++) {
            int kc = k0 + wn + nt*8 + 2*tg;
            float2 m0 = *reinterpret_cast<const float2*>(mask + (size_t)(b*Sc + qr0)*Skv + kc);
            float2 m1 = *reinterpret_cast<const float2*>(mask + (size_t)(b*Sc + qr1)*Skv + kc);
            float2 o0; o0.x = acc[mt][nt][0] + m0.x; o0.y = acc[mt][nt][1] + m0.y;
            float2 o1; o1.x = acc[mt][nt][2] + m1.x; o1.y = acc[mt][nt][3] + m1.y;
            *reinterpret_cast<float2*>(out + ((size_t)z*Sc + qr0)*Skv + kc) = o0;
            *reinterpret_cast<float2*>(out + ((size_t)z*Sc + qr1)*Skv + kc) = o1;
        }
    }
}

// ---------------- row softmax (warp per row) ----------------
__global__ void k_softmax(float* __restrict__ s, int L) {
    int row  = blockIdx.x * 8 + (threadIdx.x >> 5);
    int lane = threadIdx.x & 31;
    float* p = s + (size_t)row * L;
    float m = -3.4e38f;
    for (int i = lane; i < L; i += 32) m = fmaxf(m, p[i]);
    #pragma unroll
    for (int off = 16; off > 0; off >>= 1) m = fmaxf(m, __shfl_xor_sync(0xffffffffu, m, off));
    float sum = 0.f;
    for (int i = lane; i < L; i += 32) { float e = __expf(p[i] - m); p[i] = e; sum += e; }
    #pragma unroll
    for (int off = 16; off > 0; off >>= 1) sum += __shfl_xor_sync(0xffffffffu, sum, off);
    float inv = 1.f / sum;
    for (int i = lane; i < L; i += 32) p[i] *= inv;
}

// ---------------- attention: ctx = P V (tf32 mma) ----------------
__global__ void __launch_bounds__(256)
k_pv(const float* __restrict__ sm, const float* __restrict__ v,
     float* __restrict__ ctx, int Skv)
{
    int z = blockIdx.z;
    int b = z / NHc, h = z % NHc, kvh = h >> 2;
    int q0 = blockIdx.x * 64;
    __shared__ unsigned Ps[64][72];
    __shared__ unsigned Vs[64][72];
    int tid = threadIdx.x, lane = tid & 31, wid = tid >> 5;
    int g = lane >> 2, tg = lane & 3;
    int wm = (wid >> 2) * 32, wn = (wid & 3) * 16;

    float acc[2][2][4];
    #pragma unroll
    for (int i = 0; i < 2; i++)
        #pragma unroll
        for (int j = 0; j < 2; j++)
            #pragma unroll
            for (int p = 0; p < 4; p++) acc[i][j][p] = 0.f;

    for (int kc = 0; kc < Skv; kc += 64) {
        #pragma unroll
        for (int i = 0; i < 4; i++) {
            int c = tid + i*256;
            int r = c >> 4, cc = (c & 15) << 2;
            float4 pv = *reinterpret_cast<const float4*>(
                sm + ((size_t)z*Sc + q0 + r)*Skv + kc + cc);
            Ps[r][cc]=f2tf(pv.x); Ps[r][cc+1]=f2tf(pv.y); Ps[r][cc+2]=f2tf(pv.z); Ps[r][cc+3]=f2tf(pv.w);
            float4 vv = *reinterpret_cast<const float4*>(
                v + (size_t)(b*Skv + kc + r)*KVDc + kvh*HDc + cc);
            Vs[r][cc]=f2tf(vv.x); Vs[r][cc+1]=f2tf(vv.y); Vs[r][cc+2]=f2tf(vv.z); Vs[r][cc+3]=f2tf(vv.w);
        }
        __syncthreads();

        #pragma unroll
        for (int kb = 0; kb < 64; kb += 8) {
            unsigned af[2][4], bf[2][2];
            #pragma unroll
            for (int mt = 0; mt < 2; mt++) {
                int m0 = wm + mt*16;
                af[mt][0] = Ps[m0 + g    ][kb + tg    ];
                af[mt][1] = Ps[m0 + g + 8][kb + tg    ];
                af[mt][2] = Ps[m0 + g    ][kb + tg + 4];
                af[mt][3] = Ps[m0 + g + 8][kb + tg + 4];
            }
            #pragma unroll
            for (int nt = 0; nt < 2; nt++) {
                int n0 = wn + nt*8 + g;
                bf[nt][0] = Vs[kb + tg    ][n0];
                bf[nt][1] = Vs[kb + tg + 4][n0];
            }
            #pragma unroll
            for (int mt = 0; mt < 2; mt++)
                #pragma unroll
                for (int nt = 0; nt < 2; nt++)
                    mma_tf32(acc[mt][nt], af[mt], bf[nt]);
        }
        __syncthreads();
    }

    #pragma unroll
    for (int mt = 0; mt < 2; mt++) {
        int qr0 = q0 + wm + mt*16 + g;
        int qr1 = qr0 + 8;
        #pragma unroll
        for (int nt = 0; nt < 2; nt++) {
            int c = wn + nt*8 + 2*tg;
            float2 o0; o0.x = acc[mt][nt][0]; o0.y = acc[mt][nt][1];
            float2 o1; o1.x = acc[mt][nt][2]; o1.y = acc[mt][nt][3];
            *reinterpret_cast<float2*>(ctx + (size_t)(b*Sc + qr0)*Dc + h*HDc + c) = o0;
            *reinterpret_cast<float2*>(ctx + (size_t)(b*Sc + qr1)*Dc + h*HDc + c) = o1;
        }
    }
}

// ---------------- MoE: fused up-projection + gelu gating ----------------
// Per block: 128x64 tiles of BOTH x@w1 and x@w3 (shared A pipeline), epilogue
// writes h = gelu(t1)*t3 directly. 3-stage cp.async.
__global__ void __launch_bounds__(256)
k_moe_upact(const float* __restrict__ x, const float* __restrict__ w1,
            const float* __restrict__ w3, float* __restrict__ hout)
{
    int p = blockIdx.z;
    if (g_coef[p] == 0.f) return;
    int e = p / Bc, b = p % Bc;
    const float* A  = x  + (size_t)b*Sc*Dc;
    const float* B1 = w1 + (size_t)e*Dc*DEc;
    const float* B3 = w3 + (size_t)e*Dc*DEc;
    float* H = hout + (size_t)p*Sc*DEc;

    constexpr int STAGES = 3;
    __shared__ unsigned As [STAGES][128][20];
    __shared__ unsigned B1s[STAGES][16][72];
    __shared__ unsigned B3s[STAGES][16][72];

    int tid = threadIdx.x, wid = tid >> 5, lane = tid & 31;
    int g = lane >> 2, tg = lane & 3;
    int wm = (wid >> 2) * 64, wn = (wid & 3) * 16;
    int bm = blockIdx.y * 128, bn = blockIdx.x * 64;

    float acc1[4][2][4], acc3[4][2][4];
    #pragma unroll
    for (int i = 0; i < 4; i++)
        #pragma unroll
        for (int j = 0; j < 2; j++)
            #pragma unroll
            for (int q = 0; q < 4; q++) { acc1[i][j][q] = 0.f; acc3[i][j][q] = 0.f; }

    auto issue = [&](int s, int k0) {
        #pragma unroll
        for (int i = 0; i < 2; i++) {
            int c = tid + i*256;
            int row = c >> 2, cc = (c & 3) * 4;
            cp16(&As[s][row][cc], A + (size_t)(bm + row)*Dc + k0 + cc);
        }
        int row = tid >> 4, cc = (tid & 15) * 4;
        cp16(&B1s[s][row][cc], B1 + (size_t)(k0 + row)*DEc + bn + cc);
        cp16(&B3s[s][row][cc], B3 + (size_t)(k0 + row)*DEc + bn + cc);
    };

    const int NSTEPS = Dc / 16;
    #pragma unroll
    for (int s = 0; s < STAGES-1; s++) { issue(s, s*16); cp_commit(); }

    for (int k = 0; k < NSTEPS; k++) {
        cp_wait<STAGES-2>();
        __syncthreads();
        int ls = k + STAGES - 1;
        if (ls < NSTEPS) issue(ls % STAGES, ls * 16);
        cp_commit();

        int s = k % STAGES;
        #pragma unroll
        for (int ks = 0; ks < 2; ks++) {
            int kb = ks * 8;
            unsigned af[4][4], b1f[2][2], b3f[2][2];
            #pragma unroll
            for (int mt = 0; mt < 4; mt++) {
                int m0 = wm + mt*16;
                af[mt][0] = As[s][m0 + g    ][kb + tg    ];
                af[mt][1] = As[s][m0 + g + 8][kb + tg    ];
                af[mt][2] = As[s][m0 + g    ][kb + tg + 4];
                af[mt][3] = As[s][m0 + g + 8][kb + tg + 4];
            }
            #pragma unroll
            for (int nt = 0; nt < 2; nt++) {
                int n0 = wn + nt*8 + g;
                b1f[nt][0] = B1s[s][kb + tg    ][n0];
                b1f[nt][1] = B1s[s][kb + tg + 4][n0];
                b3f[nt][0] = B3s[s][kb + tg    ][n0];
                b3f[nt][1] = B3s[s][kb + tg + 4][n0];
            }
            #pragma unroll
            for (int mt = 0; mt < 4; mt++)
                #pragma unroll
                for (int nt = 0; nt < 2; nt++) {
                    mma_tf32(acc1[mt][nt], af[mt], b1f[nt]);
                    mma_tf32(acc3[mt][nt], af[mt], b3f[nt]);
                }
        }
    }

    #pragma unroll
    for (int mt = 0; mt < 4; mt++) {
        int r0 = bm + wm + mt*16 + g;
        int r1 = r0 + 8;
        #pragma unroll
        for (int nt = 0; nt < 2; nt++) {
            int c = bn + wn + nt*8 + 2*tg;
            float2 o0, o1;
            o0.x = gelu_exact(acc1[mt][nt][0]) * acc3[mt][nt][0];
            o0.y = gelu_exact(acc1[mt][nt][1]) * acc3[mt][nt][1];
            o1.x = gelu_exact(acc1[mt][nt][2]) * acc3[mt][nt][2];
            o1.y = gelu_exact(acc1[mt][nt][3]) * acc3[mt][nt][3];
            *reinterpret_cast<float2*>(H + (size_t)r0*DEc + c) = o0;
            *reinterpret_cast<float2*>(H + (size_t)r1*DEc + c) = o1;
        }
    }
}

__global__ void __launch_bounds__(256)
k_moe_down(const float* __restrict__ h, const float* __restrict__ W,
           float* __restrict__ out)
{
    int p = blockIdx.z;
    if (g_coef[p] == 0.f) return;
    int e = p / Bc;
    mma_core<128,128,64,32,3>(h + (size_t)p*Sc*DEc, W + (size_t)e*DEc*Dc,
                              out + (size_t)p*Sc*Dc, Dc, DEc,
                              nullptr, nullptr, 1.f, 0,
                              blockIdx.y*128, blockIdx.x*128);
}

__global__ void k_final(const float* __restrict__ res, const float* __restrict__ pout,
                        float* __restrict__ out)
{
    int idx = blockIdx.x * 256 + threadIdx.x;
    int b   = idx / (Sc*Dc);
    int off = idx - b*(Sc*Dc);
    float v = res[idx];
    #pragma unroll
    for (int e = 0; e < NEc; e++) {
        float cf = g_coef[e*Bc + b];
        if (cf != 0.f) v += cf * pout[(size_t)(e*Bc + b)*Sc*Dc + off];
    }
    out[idx] = v;
}

// ---------------- launch ----------------
extern "C" void kernel_launch(void* const* d_in, const int* in_sizes, int n_in,
                              void* d_out, int out_size)
{
    (void)in_sizes; (void)n_in; (void)out_size;
    const float* hid   = (const float*)d_in[0];
    const float* enc   = (const float*)d_in[1];
    const float* amask = (const float*)d_in[2];
    const float* emask = (const float*)d_in[3];
    const int*   langs = (const int*)  d_in[4];
    const float* ln1g  = (const float*)d_in[5];
    const float* ln1b  = (const float*)d_in[6];
    const float* saqw  = (const float*)d_in[7];
    const float* saqb  = (const float*)d_in[8];
    const float* sakw  = (const float*)d_in[9];
    const float* sakb  = (const float*)d_in[10];
    const float* savw  = (const float*)d_in[11];
    const float* savb  = (const float*)d_in[12];
    const float* saow  = (const float*)d_in[13];
    const float* saob  = (const float*)d_in[14];
    const float* ln2g  = (const float*)d_in[15];
    const float* ln2b  = (const float*)d_in[16];
    const float* caqw  = (const float*)d_in[17];
    const float* caqb  = (const float*)d_in[18];
    const float* cakw  = (const float*)d_in[19];
    const float* cakb  = (const float*)d_in[20];
    const float* cavw  = (const float*)d_in[21];
    const float* cavb  = (const float*)d_in[22];
    const float* caow  = (const float*)d_in[23];
    const float* caob  = (const float*)d_in[24];
    const float* ln3g  = (const float*)d_in[25];
    const float* ln3b  = (const float*)d_in[26];
    const float* w1    = (const float*)d_in[27];
    const float* w2    = (const float*)d_in[28];
    const float* w3    = (const float*)d_in[29];
    float* out = (float*)d_out;

    float *p_ln, *p_q, *p_k, *p_v, *p_s, *p_ctx, *p_res, *p_t1, *p_pout;
    cudaGetSymbolAddress((void**)&p_ln,   g_ln);
    cudaGetSymbolAddress((void**)&p_q,    g_q);
    cudaGetSymbolAddress((void**)&p_k,    g_k);
    cudaGetSymbolAddress((void**)&p_v,    g_v);
    cudaGetSymbolAddress((void**)&p_s,    g_sc);
    cudaGetSymbolAddress((void**)&p_ctx,  g_ctx);
    cudaGetSymbolAddress((void**)&p_res,  g_res);
    cudaGetSymbolAddress((void**)&p_t1,   g_t1);
    cudaGetSymbolAddress((void**)&p_pout, g_pout);

    const int M  = Bc*Sc;      // 1024

    k_route<<<1, 32>>>(langs);

    // ===== self attention (causal GQA) =====
    k_ln<<<M, 256>>>(hid, ln1g, ln1b, p_ln);
    // Q: 16x16=256 blocks; K,V: 16x4=64 each -> 384
    k_qkv<<<384, 256>>>(p_ln, M/64, p_ln, M/64,
                        saqw, saqb, sakw, sakb, savw, savb, p_q, p_k, p_v);
    k_scores<<<dim3(Sc/64, Sc/64, Bc*NHc), 256>>>(p_q, p_k, amask, p_s, Sc);
    k_softmax<<<(Bc*NHc*Sc)/8, 256>>>(p_s, Sc);
    k_pv<<<dim3(Sc/64, 1, Bc*NHc), 256>>>(p_s, p_v, p_ctx, Sc);
    k_gemm64<<<dim3(Dc/64, M/64), 256>>>(p_ctx, saow, p_res, Dc, Dc, saob, hid, 1.f, 3);

    // ===== cross attention over encoder states =====
    k_ln<<<M, 256>>>(p_res, ln2g, ln2b, p_ln);
    // Q: 256 blocks; K,V over enc (2048 rows): 32x4=128 each -> 512
    k_qkv<<<512, 256>>>(p_ln, M/64, enc, (Bc*SKc)/64,
                        caqw, caqb, cakw, cakb, cavw, cavb, p_q, p_k, p_v);
    k_scores<<<dim3(Sc/64, SKc/64, Bc*NHc), 256>>>(p_q, p_k, emask, p_s, SKc);
    k_softmax<<<(Bc*NHc*Sc)/8, 256>>>(p_s, SKc);
    k_pv<<<dim3(Sc/64, 1, Bc*NHc), 256>>>(p_s, p_v, p_ctx, SKc);
    k_gemm64<<<dim3(Dc/64, M/64), 256>>>(p_ctx, caow, p_res, Dc, Dc, caob, p_res, 1.f, 3);

    // ===== language-routed MoE FFN =====
    k_ln<<<M, 256>>>(p_res, ln3g, ln3b, p_ln);
    k_moe_upact<<<dim3(DEc/64, Sc/128, NEc*Bc), 256>>>(p_ln, w1, w3, p_t1);
    k_moe_down<<<dim3(Dc/128, Sc/128, NEc*Bc), 256>>>(p_t1, w2, p_pout);
    k_final<<<(Bc*Sc*Dc)/256, 256>>>(p_res, p_pout, out);
}